// round 16
// baseline (speedup 1.0000x reference)
#include <cuda_runtime.h>
#include <cstdint>

// Problem constants (fixed by the reference)
#define H            8
#define NUM_DRAM     4096
#define NUM_HBM      819          // int(4096 * 0.2)
#define TOPK         256
#define PAGE_SIZE    16
#define HEAD_DIM     128
#define PAGE_ELEMS   4096         // 16 * 2 * 128
#define SEQ_PER_HEAD (NUM_HBM * PAGE_SIZE)              // 13104
#define KELEMS_HEAD  ((size_t)SEQ_PER_HEAD * HEAD_DIM)  // 1,677,312
#define KTOTAL       ((size_t)H * KELEMS_HEAD)          // 13,418,496

#define PAGES_PER_BLK 8           // 8 warps: one slot-rank per warp, then copy 8 pages
#define SUBS_PER_HEAD 104         // 104*8 = 832 >= 819 slots per head
#define GRID_BLOCKS   (H * SUBS_PER_HEAD)   // 832 — single co-resident wave at 8/SM

// ---------------------------------------------------------------------------
// ONE kernel, fully partitioned: block b owns 8 slots of one head and
//   (1) computes the LRU decision for exactly those 8 slots
//   (2) copies exactly those 8 pages.
// NO inter-block communication (R8-R12 lesson: global sync costs ~10us).
// Pure function of inputs => deterministic, graph-replay-safe by construction.
//
// R15 lesson: explicit front-batch buffers pushed regs 32->40, occupancy
// 60%, DRAM 59%. This version uses the R2/R4-proven copy body (plain
// unrolled load/store loop, ptxas front-batches on its own at 32 regs) and
// __launch_bounds__(256,8) to pin the allocation.
//
// Emulates the reference exactly, incl. JAX's negative-index WRAPPING in
// scatters (idx=-1 -> slot 818, applied before mode='drop'):
//   slot = d2h[topk];  pat[slot>=0 ? slot : 818] = step_f
//   stable rank(i) over pat;  slot i is a victim iff rank(i) < n_miss,
//   receiving the page of the rank(i)-th miss (inverse of order[] scatter).
//   Hits scatter to wrapped slot 818, last hit wins (818 is never a victim:
//   pat[818]==step_f puts its rank above any possible n_miss).
// ---------------------------------------------------------------------------
__global__ void __launch_bounds__(256, 8) lru_fused_kernel(
    const float* __restrict__ dram,
    const float* __restrict__ hbm,
    const float* __restrict__ pat_g,
    const int*   __restrict__ d2h_g,
    const int*   __restrict__ topk_g,
    const int*   __restrict__ step_g,
    float*       __restrict__ kout,
    float*       __restrict__ vout)
{
    __shared__ float pat_s[NUM_HBM];
    __shared__ int   miss_page[TOPK];
    __shared__ int   warp_pre[TOPK / 32];
    __shared__ int   n_miss_s, last_hit_s, last_hit_page_s;
    __shared__ int   sp_s[PAGES_PER_BLK];

    const int b      = blockIdx.x;
    const int h      = b / SUBS_PER_HEAD;
    const int sub    = b - h * SUBS_PER_HEAD;
    const int s_base = sub * PAGES_PER_BLK;       // first slot this block owns
    const int t      = threadIdx.x;               // 0..255
    const int warp   = t >> 5;
    const int lane   = t & 31;
    const float step_f = (float)(step_g[0] + 1);

    // ---------------- Control state (replicated per block, ~1-2us) ---------
    if (t == 0) { last_hit_s = -1; last_hit_page_s = -1; }
    for (int i = t; i < NUM_HBM; i += 256)
        pat_s[i] = pat_g[h * NUM_HBM + i];

    // Every thread owns one topk entry
    const int p    = topk_g[h * TOPK + t];
    const int slot = d2h_g[h * NUM_DRAM + p];
    const bool miss = (slot < 0);
    const unsigned mm = __ballot_sync(0xFFFFFFFFu, miss);
    const int wpre = __popc(mm & ((1u << lane) - 1u));
    if (lane == 0) warp_pre[warp] = __popc(mm);
    if (!miss) atomicMax(&last_hit_s, t);
    __syncthreads();

    // pat scatter with wrapped negative index (all writes = step_f; races benign)
    pat_s[miss ? (NUM_HBM - 1) : slot] = step_f;
    if (t == 0) {                        // scan the 8 warp miss-counts
        int c = 0;
        #pragma unroll
        for (int w = 0; w < TOPK / 32; w++) { const int x = warp_pre[w]; warp_pre[w] = c; c += x; }
        n_miss_s = c;
    }
    __syncthreads();

    if (miss) miss_page[warp_pre[warp] + wpre] = p;
    if (t == last_hit_s) last_hit_page_s = p;
    __syncthreads();

    // ---------------- Rank ONLY this block's 8 slots (one per warp) --------
    const int i = s_base + warp;                  // warp < 8
    if (i < NUM_HBM) {
        const float vi = pat_s[i];
        int r = 0;
        #pragma unroll 2
        for (int j = lane; j < NUM_HBM; j += 32) {
            const float vj = pat_s[j];
            r += (vj < vi) || (vj == vi && j < i);
        }
        r = __reduce_add_sync(0xFFFFFFFFu, r);
        if (lane == 0) {
            int sp = (r < n_miss_s) ? miss_page[r] : -1;
            if (i == NUM_HBM - 1 && last_hit_page_s >= 0) sp = last_hit_page_s;
            sp_s[warp] = sp;
        }
    }
    __syncthreads();

    // ---------------- Copy this block's 8 pages (proven 30.1us body) -------
    // src elem e = row*256 + kv*128 + d  ->  k/v[h, s*16+row, d].
    for (int j = 0; j < PAGES_PER_BLK; j++) {
        const int s = s_base + j;
        if (s >= NUM_HBM) break;
        const int sp  = sp_s[j];
        const int pid = h * NUM_HBM + s;

        const float4* __restrict__ src = (const float4*)(
            (sp >= 0) ? (dram + ((size_t)h * NUM_DRAM + (size_t)sp) * PAGE_ELEMS)
                      : (hbm  + (size_t)pid * PAGE_ELEMS));

        float4* __restrict__ kbase =
            (float4*)(kout + ((size_t)h * SEQ_PER_HEAD + (size_t)s * PAGE_SIZE) * HEAD_DIM);
        float4* __restrict__ vbase =
            (float4*)(vout + ((size_t)h * SEQ_PER_HEAD + (size_t)s * PAGE_SIZE) * HEAD_DIM);

        // 1024 float4 per page; 4 independent 16B ops per thread (MLP=4).
        #pragma unroll 4
        for (int f = t; f < PAGE_ELEMS / 4; f += 256) {
            const float4 val = src[f];
            const int row = f >> 6;
            const int dd  = f & 31;
            if ((f >> 5) & 1) vbase[row * 32 + dd] = val;
            else              kbase[row * 32 + dd] = val;
        }
    }
}

// ---------------------------------------------------------------------------
// Launch: single kernel, graph-capture friendly, allocation-free, stateless.
// ---------------------------------------------------------------------------
extern "C" void kernel_launch(void* const* d_in, const int* in_sizes, int n_in,
                              void* d_out, int out_size)
{
    const float* dram = (const float*)d_in[0];   // (H, 4096, 4096) f32
    const float* hbm  = (const float*)d_in[1];   // (H, 819, 4096)  f32
    const float* pat  = (const float*)d_in[2];   // (H, 819)        f32
    const int*   d2h  = (const int*)  d_in[3];   // (H, 4096)       i32
    // d_in[4] = h2d (never affects the returned k/v caches)
    const int*   topk = (const int*)  d_in[5];   // (H, 256)        i32
    const int*   step = (const int*)  d_in[6];   // (1,)            i32

    float* kout = (float*)d_out;
    float* vout = (float*)d_out + KTOTAL;

    lru_fused_kernel<<<GRID_BLOCKS, 256>>>(dram, hbm, pat, d2h, topk, step, kout, vout);
}

// round 17
// speedup vs baseline: 1.0357x; 1.0357x over previous
#include <cuda_runtime.h>
#include <cstdint>

// Problem constants (fixed by the reference)
#define H            8
#define NUM_DRAM     4096
#define NUM_HBM      819          // int(4096 * 0.2)
#define TOPK         256
#define PAGE_SIZE    16
#define HEAD_DIM     128
#define PAGE_ELEMS   4096         // 16 * 2 * 128
#define SEQ_PER_HEAD (NUM_HBM * PAGE_SIZE)              // 13104
#define KELEMS_HEAD  ((size_t)SEQ_PER_HEAD * HEAD_DIM)  // 1,677,312
#define KTOTAL       ((size_t)H * KELEMS_HEAD)          // 13,418,496

#define PAGES_PER_BLK 4           // warps 0-3 rank one slot each, block copies 4 pages
#define SUBS_PER_HEAD 205         // 205*4 = 820 >= 819 slots per head
#define GRID_BLOCKS   (H * SUBS_PER_HEAD)   // 1640 — fills 148 SMs at 8 blocks/SM+

// ---------------------------------------------------------------------------
// ONE kernel, fully partitioned: block b owns 4 slots of one head and
//   (1) computes the LRU decision for exactly those 4 slots
//   (2) copies exactly those 4 pages.
// NO inter-block communication (R8-R12: global sync costs ~10us).
// Pure function of inputs => deterministic, graph-replay-safe by construction.
//
// Grid-size tradeoff (measured): 832 blocks -> copy phase starved (occ 64%,
// DRAM 57%); 6552 blocks -> prologue replication dominates (+12us). 1640
// blocks doubles copy-phase parallelism while prologue replication stays
// ~2x of the proven-cheap R15 level; wave-2 prologues overlap wave-1 copies.
//
// Emulates the reference exactly, incl. JAX's negative-index WRAPPING in
// scatters (idx=-1 -> slot 818, applied before mode='drop'):
//   slot = d2h[topk];  pat[slot>=0 ? slot : 818] = step_f
//   stable rank(i) over pat;  slot i is a victim iff rank(i) < n_miss,
//   receiving the page of the rank(i)-th miss (inverse of order[] scatter).
//   Hits scatter to wrapped slot 818, last hit wins (818 is never a victim:
//   pat[818]==step_f puts its rank above any possible n_miss).
// ---------------------------------------------------------------------------
__global__ void __launch_bounds__(256, 8) lru_fused_kernel(
    const float* __restrict__ dram,
    const float* __restrict__ hbm,
    const float* __restrict__ pat_g,
    const int*   __restrict__ d2h_g,
    const int*   __restrict__ topk_g,
    const int*   __restrict__ step_g,
    float*       __restrict__ kout,
    float*       __restrict__ vout)
{
    __shared__ float pat_s[NUM_HBM];
    __shared__ int   miss_page[TOPK];
    __shared__ int   warp_pre[TOPK / 32];
    __shared__ int   n_miss_s, last_hit_s, last_hit_page_s;
    __shared__ int   sp_s[PAGES_PER_BLK];

    const int b      = blockIdx.x;
    const int h      = b / SUBS_PER_HEAD;
    const int sub    = b - h * SUBS_PER_HEAD;
    const int s_base = sub * PAGES_PER_BLK;       // first slot this block owns
    const int t      = threadIdx.x;               // 0..255
    const int warp   = t >> 5;
    const int lane   = t & 31;
    const float step_f = (float)(step_g[0] + 1);

    // ---------------- Control state (replicated per block) -----------------
    if (t == 0) { last_hit_s = -1; last_hit_page_s = -1; }
    for (int i = t; i < NUM_HBM; i += 256)
        pat_s[i] = pat_g[h * NUM_HBM + i];

    // Every thread owns one topk entry
    const int p    = topk_g[h * TOPK + t];
    const int slot = d2h_g[h * NUM_DRAM + p];
    const bool miss = (slot < 0);
    const unsigned mm = __ballot_sync(0xFFFFFFFFu, miss);
    const int wpre = __popc(mm & ((1u << lane) - 1u));
    if (lane == 0) warp_pre[warp] = __popc(mm);
    if (!miss) atomicMax(&last_hit_s, t);
    __syncthreads();

    // pat scatter with wrapped negative index (all writes = step_f; races benign)
    pat_s[miss ? (NUM_HBM - 1) : slot] = step_f;
    if (t == 0) {                        // scan the 8 warp miss-counts
        int c = 0;
        #pragma unroll
        for (int w = 0; w < TOPK / 32; w++) { const int x = warp_pre[w]; warp_pre[w] = c; c += x; }
        n_miss_s = c;
    }
    __syncthreads();

    if (miss) miss_page[warp_pre[warp] + wpre] = p;
    if (t == last_hit_s) last_hit_page_s = p;
    __syncthreads();

    // ---------------- Rank ONLY this block's 4 slots (warps 0-3) -----------
    if (warp < PAGES_PER_BLK) {
        const int i = s_base + warp;
        if (i < NUM_HBM) {
            const float vi = pat_s[i];
            int r = 0;
            #pragma unroll 2
            for (int j = lane; j < NUM_HBM; j += 32) {
                const float vj = pat_s[j];
                r += (vj < vi) || (vj == vi && j < i);
            }
            r = __reduce_add_sync(0xFFFFFFFFu, r);
            if (lane == 0) {
                int sp = (r < n_miss_s) ? miss_page[r] : -1;
                if (i == NUM_HBM - 1 && last_hit_page_s >= 0) sp = last_hit_page_s;
                sp_s[warp] = sp;
            }
        }
    }
    __syncthreads();

    // ---------------- Copy this block's 4 pages (proven 30.1us body) -------
    // src elem e = row*256 + kv*128 + d  ->  k/v[h, s*16+row, d].
    for (int j = 0; j < PAGES_PER_BLK; j++) {
        const int s = s_base + j;
        if (s >= NUM_HBM) break;
        const int sp  = sp_s[j];
        const int pid = h * NUM_HBM + s;

        const float4* __restrict__ src = (const float4*)(
            (sp >= 0) ? (dram + ((size_t)h * NUM_DRAM + (size_t)sp) * PAGE_ELEMS)
                      : (hbm  + (size_t)pid * PAGE_ELEMS));

        float4* __restrict__ kbase =
            (float4*)(kout + ((size_t)h * SEQ_PER_HEAD + (size_t)s * PAGE_SIZE) * HEAD_DIM);
        float4* __restrict__ vbase =
            (float4*)(vout + ((size_t)h * SEQ_PER_HEAD + (size_t)s * PAGE_SIZE) * HEAD_DIM);

        // 1024 float4 per page; 4 independent 16B ops per thread (MLP=4).
        #pragma unroll 4
        for (int f = t; f < PAGE_ELEMS / 4; f += 256) {
            const float4 val = src[f];
            const int row = f >> 6;
            const int dd  = f & 31;
            if ((f >> 5) & 1) vbase[row * 32 + dd] = val;
            else              kbase[row * 32 + dd] = val;
        }
    }
}

// ---------------------------------------------------------------------------
// Launch: single kernel, graph-capture friendly, allocation-free, stateless.
// ---------------------------------------------------------------------------
extern "C" void kernel_launch(void* const* d_in, const int* in_sizes, int n_in,
                              void* d_out, int out_size)
{
    const float* dram = (const float*)d_in[0];   // (H, 4096, 4096) f32
    const float* hbm  = (const float*)d_in[1];   // (H, 819, 4096)  f32
    const float* pat  = (const float*)d_in[2];   // (H, 819)        f32
    const int*   d2h  = (const int*)  d_in[3];   // (H, 4096)       i32
    // d_in[4] = h2d (never affects the returned k/v caches)
    const int*   topk = (const int*)  d_in[5];   // (H, 256)        i32
    const int*   step = (const int*)  d_in[6];   // (1,)            i32

    float* kout = (float*)d_out;
    float* vout = (float*)d_out + KTOTAL;

    lru_fused_kernel<<<GRID_BLOCKS, 256>>>(dram, hbm, pat, d2h, topk, step, kout, vout);
}